// round 6
// baseline (speedup 1.0000x reference)
#include <cuda_runtime.h>
#include <cuda_bf16.h>
#include <math.h>
#include <stdint.h>

#define G_   64
#define T_   10
#define H_   256
#define H4_  1024

// Output offsets (tuple flattened: gamma, beta, delta, hN, cN)
#define OFF_GAMMA 0
#define OFF_BETA  640
#define OFF_DELTA 164480
#define OFF_HN    328320
#define OFF_CN    361088

// Scratch
__device__ float g_h2  [G_ * T_ * H_];
__device__ float g_lin1[G_ * T_ * H_];
__device__ int   g_dummy;

__device__ __forceinline__ float fast_tanh(float x) {
    float r;
    asm("tanh.approx.f32 %0, %1;" : "=f"(r) : "f"(x));
    return r;
}
__device__ __forceinline__ float sigf(float x) {
    return __fdividef(1.0f, 1.0f + __expf(-x));
}
__device__ __forceinline__ void fma2(unsigned long long& acc, unsigned long long a, unsigned long long b) {
    asm("fma.rn.f32x2 %0, %1, %2, %0;" : "+l"(acc) : "l"(a), "l"(b));
}
__device__ __forceinline__ float unpack_sum(unsigned long long v) {
    unsigned int lo, hi;
    asm("mov.b64 {%0, %1}, %2;" : "=r"(lo), "=r"(hi) : "l"(v));
    return __uint_as_float(lo) + __uint_as_float(hi);
}
__device__ __forceinline__ unsigned int smem_u32(const void* p) {
    unsigned int a;
    asm("{ .reg .u64 t; cvta.to.shared.u64 t, %1; cvt.u32.u64 %0, t; }" : "=r"(a) : "l"(p));
    return a;
}
__device__ __forceinline__ void st_cluster_f32(unsigned int saddr, unsigned int rank, float v) {
    unsigned int r;
    asm volatile("mapa.shared::cluster.u32 %0, %1, %2;" : "=r"(r) : "r"(saddr), "r"(rank));
    asm volatile("st.shared::cluster.f32 [%0], %1;" :: "r"(r), "f"(v) : "memory");
}
#define CLUSTER_SYNC() do { \
    asm volatile("barrier.cluster.arrive.aligned;" ::: "memory"); \
    asm volatile("barrier.cluster.wait.aligned;"   ::: "memory"); } while (0)

__device__ __forceinline__ void bulk_g2s(unsigned int dst, const void* src,
                                         unsigned int bytes, unsigned int mbar) {
    asm volatile(
        "cp.async.bulk.shared::cluster.global.mbarrier::complete_tx::bytes [%0], [%1], %2, [%3];"
        :: "r"(dst), "l"(src), "r"(bytes), "r"(mbar) : "memory");
}
__device__ __forceinline__ void mbar_init(unsigned int addr, unsigned int cnt) {
    asm volatile("mbarrier.init.shared.b64 [%0], %1;" :: "r"(addr), "r"(cnt) : "memory");
}
__device__ __forceinline__ void mbar_expect(unsigned int addr, unsigned int bytes) {
    asm volatile("mbarrier.arrive.expect_tx.shared.b64 _, [%0], %1;" :: "r"(addr), "r"(bytes) : "memory");
}
__device__ __forceinline__ void mbar_wait(unsigned int addr, unsigned int parity) {
    unsigned int done;
    do {
        asm volatile(
            "{ .reg .pred p; mbarrier.try_wait.parity.acquire.cta.shared::cta.b64 p, [%1], %2, 0x989680; selp.b32 %0,1,0,p; }"
            : "=r"(done) : "r"(addr), "r"(parity) : "memory");
    } while (!done);
}

// Dummy kernel: aligns the ncu capture slot onto the LSTM kernel.
__global__ void dummy_kernel(int tag) {
    if (tag == 12345 && threadIdx.x == 0) g_dummy = tag;
}

// ---------------------------------------------------------------------------
// Persistent fused 2-layer LSTM. Grid: 128 CTAs = 16 clusters of 8.
// Cluster ci handles groups [4ci, 4ci+4), each group both layers, sequentially
// (8 "units"). CTA rank owns hidden units [32r,32r+32) -> 128 gate rows.
// 512 threads: row rl = tid>>2, quarter q = tid&3 (64 cols each).
// 3 rotating 64KB buffers: Wih(u) in {P[s],P[s+1]}; Whh(u) lo->P[s+2],
// hi->P[s] (after xg); Wih(u+1) -> {P[s+1],P[s+2]} during recurrence. s+=1.
// Layer-1 input (h1) is captured into xs from the per-step DSMEM broadcast.
// ---------------------------------------------------------------------------
#define SMEM_BYTES 215040

__global__ void __cluster_dims__(8, 1, 1) __launch_bounds__(512, 1)
lstm_persist_kernel(const float* __restrict__ Wih0, const float* __restrict__ Whh0,
                    const float* __restrict__ bih0, const float* __restrict__ bhh0,
                    const float* __restrict__ Wih1, const float* __restrict__ Whh1,
                    const float* __restrict__ bih1, const float* __restrict__ bhh1,
                    const float* __restrict__ data, float* __restrict__ out)
{
    extern __shared__ __align__(16) char smem[];
    float* Pb[3] = { (float*)smem, (float*)(smem + 65536), (float*)(smem + 131072) };
    float* xs     = (float*)(smem + 196608);   // 10KB swizzled input rows
    float* xgp    = (float*)(smem + 206848);   // 5KB [t][row]
    float* h_buf  = (float*)(smem + 211968);   // 2KB double buffer (swizzled)
    float* gate_s = (float*)(smem + 214016);   // 512B
    const unsigned int mb = smem_u32(smem + 214528);  // 4 mbarriers (8B each)
    // mb+0: wih_lo, mb+8: wih_hi, mb+16: whh_lo, mb+24: whh_hi

    const int ci   = blockIdx.x >> 3;
    const int rank = blockIdx.x & 7;
    const int tid  = threadIdx.x;
    const int rl   = tid >> 2;
    const int q    = tid & 3;
    const int gate = rl >> 5;
    const int ul   = rl & 31;
    const int qh   = q ^ (q << 1);

    if (tid == 0) {
        mbar_init(mb + 0, 1); mbar_init(mb + 8, 1);
        mbar_init(mb + 16, 1); mbar_init(mb + 24, 1);
    }
    __syncthreads();

    // ---- prefetch Wih(unit 0) and xs = data for group 4ci ----
    {
        const int g0 = ci * 4;
        if (tid == 0) {
            mbar_expect(mb + 0, 65536);
            bulk_g2s(smem_u32(Pb[0]),         Wih0 + ((size_t)g0 * 1024 +   0 + rank * 32) * 256, 32768, mb + 0);
            bulk_g2s(smem_u32(Pb[0]) + 32768, Wih0 + ((size_t)g0 * 1024 + 256 + rank * 32) * 256, 32768, mb + 0);
            mbar_expect(mb + 8, 65536);
            bulk_g2s(smem_u32(Pb[1]),         Wih0 + ((size_t)g0 * 1024 + 512 + rank * 32) * 256, 32768, mb + 8);
            bulk_g2s(smem_u32(Pb[1]) + 32768, Wih0 + ((size_t)g0 * 1024 + 768 + rank * 32) * 256, 32768, mb + 8);
        }
        for (int e = tid; e < T_ * 256; e += 512) {
            int t = e >> 8, u = e & 255;
            xs[t * 256 + (u ^ ((u & 0xC0) >> 3))] = data[((size_t)t * G_ + g0) * 256 + u];
        }
    }
    // RACE FIX (round-5 bug): unit-0 xg reads ALL of xs; the fill above is
    // per-thread strided. Must barrier before any thread consumes xs.
    __syncthreads();

    int slot = 0;
    for (int un = 0; un < 8; un++) {
        const int gi    = un >> 1;
        const int layer = un & 1;
        const int g     = ci * 4 + gi;
        const int par   = un & 1;
        const float* Whh  = layer ? Whh1 : Whh0;
        const float* bihp = layer ? bih1 : bih0;
        const float* bhhp = layer ? bhh1 : bhh0;
        float* Pwl = Pb[slot];
        float* Pwh = Pb[(slot + 1) % 3];
        float* Phl = Pb[(slot + 2) % 3];
        float* Phh = Pwl;
        const int grow = gate * 256 + rank * 32 + ul;

        // issue Whh lo (gates 0,1) -> Phl (free since unit-1's wreg copy)
        if (tid == 0) {
            mbar_expect(mb + 16, 65536);
            bulk_g2s(smem_u32(Phl),         Whh + ((size_t)g * 1024 +   0 + rank * 32) * 256, 32768, mb + 16);
            bulk_g2s(smem_u32(Phl) + 32768, Whh + ((size_t)g * 1024 + 256 + rank * 32) * 256, 32768, mb + 16);
        }

        // wait own Wih half (lo rows <-> mb0/Pwl, hi rows <-> mb8/Pwh)
        mbar_wait(rl < 64 ? mb + 0 : mb + 8, par);

        // ---- input projection from SMEM ----
        const ulonglong2* wsrc = (const ulonglong2*)((rl < 64) ? (Pwl + rl * 256)
                                                               : (Pwh + (rl - 64) * 256));
        const ulonglong2* xs2 = (const ulonglong2*)xs;
        unsigned long long xa[T_];
        #pragma unroll
        for (int t = 0; t < T_; t++) xa[t] = 0ull;
        #pragma unroll 2
        for (int i = 0; i < 16; i++) {
            ulonglong2 w = wsrc[16 * q + (i ^ q)];
            const int xi = 16 * q + (i ^ qh);
            #pragma unroll
            for (int t = 0; t < T_; t++) {
                ulonglong2 x = xs2[t * 64 + xi];
                fma2(xa[t], w.x, x.x);
                fma2(xa[t], w.y, x.y);
            }
        }
        const float bias = (q == 0)
            ? bihp[(size_t)g * H4_ + grow] + bhhp[(size_t)g * H4_ + grow] : 0.0f;
        #pragma unroll
        for (int t = 0; t < T_; t++) {
            float s = unpack_sum(xa[t]);
            s += __shfl_xor_sync(0xffffffffu, s, 1);
            s += __shfl_xor_sync(0xffffffffu, s, 2);
            if (q == 0) xgp[t * 128 + rl] = s + bias;
        }
        __syncthreads();   // all xg reads of Pwl/Pwh done; xgp complete

        // issue Whh hi (gates 2,3) -> Phh (= Pwl, now free)
        if (tid == 0) {
            mbar_expect(mb + 24, 65536);
            bulk_g2s(smem_u32(Phh),         Whh + ((size_t)g * 1024 + 512 + rank * 32) * 256, 32768, mb + 24);
            bulk_g2s(smem_u32(Phh) + 32768, Whh + ((size_t)g * 1024 + 768 + rank * 32) * 256, 32768, mb + 24);
        }

        // after layer-1 xg: xs is free -> prefetch next group's data
        if (layer == 1 && gi < 3) {
            const int gn = g + 1;
            for (int e = tid; e < T_ * 256; e += 512) {
                int t = e >> 8, u = e & 255;
                xs[t * 256 + (u ^ ((u & 0xC0) >> 3))] = data[((size_t)t * G_ + gn) * 256 + u];
            }
        }

        // wait Whh, copy to registers
        mbar_wait(rl < 64 ? mb + 16 : mb + 24, par);
        const ulonglong2* hsrc = (const ulonglong2*)((rl < 64) ? (Phl + rl * 256)
                                                               : (Phh + (rl - 64) * 256));
        ulonglong2 wreg[16];
        #pragma unroll
        for (int i = 0; i < 16; i++) wreg[i] = hsrc[16 * q + (i ^ q)];
        __syncthreads();   // wreg copies done -> Phl free; xgp + xs prefetch visible

        // issue next unit's Wih into {Pwh, Phl} (the next slot's {P[s'],P[s'+1]})
        if (tid == 0 && un < 7) {
            const int nl = (un + 1) & 1;
            const int gn2 = ci * 4 + ((un + 1) >> 1);
            const float* Wn = nl ? Wih1 : Wih0;
            mbar_expect(mb + 0, 65536);
            bulk_g2s(smem_u32(Pwh),         Wn + ((size_t)gn2 * 1024 +   0 + rank * 32) * 256, 32768, mb + 0);
            bulk_g2s(smem_u32(Pwh) + 32768, Wn + ((size_t)gn2 * 1024 + 256 + rank * 32) * 256, 32768, mb + 0);
            mbar_expect(mb + 8, 65536);
            bulk_g2s(smem_u32(Phl),         Wn + ((size_t)gn2 * 1024 + 512 + rank * 32) * 256, 32768, mb + 8);
            bulk_g2s(smem_u32(Phl) + 32768, Wn + ((size_t)gn2 * 1024 + 768 + rank * 32) * 256, 32768, mb + 8);
        }

        if (tid < 256) h_buf[tid] = 0.0f;   // p=0 buffer zeros (swizzle(0)=0)
        __syncthreads();
        CLUSTER_SYNC();   // zeros visible cluster-wide before DSMEM traffic

        // ---- recurrence ----
        const unsigned int hbase = smem_u32(h_buf);
        float* hdst = g_h2 + (size_t)g * T_ * 256;
        float c_reg = 0.0f, h_last = 0.0f;
        int p = 0;

        for (int t = 0; t < T_; t++) {
            // layer 0: capture h(t-1) (full, swizzled) into xs for layer-1 xg
            if (layer == 0 && t > 0 && tid < 256)
                xs[(t - 1) * 256 + tid] = h_buf[p * 256 + tid];

            const ulonglong2* h2 = (const ulonglong2*)(h_buf + p * 256);
            unsigned long long a0 = 0ull, a1 = 0ull;
            #pragma unroll
            for (int i = 0; i < 16; i++) {
                ulonglong2 h = h2[16 * q + (i ^ qh)];
                fma2(a0, wreg[i].x, h.x);
                fma2(a1, wreg[i].y, h.y);
            }
            float s = unpack_sum(a0) + unpack_sum(a1);
            s += __shfl_xor_sync(0xffffffffu, s, 1);
            s += __shfl_xor_sync(0xffffffffu, s, 2);
            if (q == 0) gate_s[rl] = s + xgp[t * 128 + rl];
            __syncthreads();

            if (tid < 32) {
                const int u = tid;
                float ig = gate_s[u];
                float fg = gate_s[32 + u];
                float gg = gate_s[64 + u];
                float og = gate_s[96 + u];
                c_reg = sigf(fg) * c_reg + sigf(ig) * fast_tanh(gg);
                float h = sigf(og) * fast_tanh(c_reg);
                h_last = h;
                if (layer) hdst[(size_t)t * 256 + rank * 32 + u] = h;
                const int gu = rank * 32 + u;
                const int phys = gu ^ ((gu & 0xC0) >> 3);
                const unsigned int dst = hbase + (unsigned)((1 - p) * 256 + phys) * 4u;
                #pragma unroll
                for (int pr = 0; pr < 8; pr++) st_cluster_f32(dst, (unsigned)pr, h);
            }
            CLUSTER_SYNC();
            p ^= 1;
        }
        // final h(T-1) capture for layer-1 xg
        if (layer == 0 && tid < 256)
            xs[(T_ - 1) * 256 + tid] = h_buf[p * 256 + tid];
        __syncthreads();

        if (tid < 32) {
            out[OFF_HN + (size_t)g * 512 + layer * 256 + rank * 32 + tid] = h_last;
            out[OFF_CN + (size_t)g * 512 + layer * 256 + rank * 32 + tid] = c_reg;
        }
        slot = (slot + 1) % 3;
    }
}

// ---------------------------------------------------------------------------
// Fused tail: per-group Wlin -> fc (SMEM) -> lin1/beta/gamma.
// Grid: 64 blocks (one per group) x 256 threads.
// ---------------------------------------------------------------------------
__global__ void __launch_bounds__(256)
tail_kernel(const float* __restrict__ Wlin, const float* __restrict__ blin,
            const float* __restrict__ W1, const float* __restrict__ b1,
            const float* __restrict__ W2, const float* __restrict__ b2,
            const float* __restrict__ Wd, const float* __restrict__ bd,
            float* __restrict__ out)
{
    __shared__ __align__(16) float hs [T_ * 256];
    __shared__ __align__(16) float fcs[T_ * 256];
    __shared__ float red[T_ * 8];

    const int g = blockIdx.x;
    const int j = threadIdx.x;
    const int lane = j & 31, warp = j >> 5;

    {
        const float4* hp4 = (const float4*)(g_h2 + (size_t)g * T_ * 256);
        float4* hw = (float4*)hs;
        for (int e = j; e < 640; e += 256) hw[e] = hp4[e];
    }
    __syncthreads();

    // fc[t][j] = dot(Wlin[g,j,:], h2[g,t,:]) + blin[g,j]
    float acc[T_];
    #pragma unroll
    for (int t = 0; t < T_; t++) acc[t] = 0.0f;
    {
        const float4* wl  = (const float4*)(Wlin + ((size_t)g * 256 + j) * 256);
        const float4* hs4 = (const float4*)hs;
        #pragma unroll 4
        for (int i4 = 0; i4 < 64; i4++) {
            float4 w = wl[i4];
            #pragma unroll
            for (int t = 0; t < T_; t++) {
                float4 f = hs4[t * 64 + i4];
                acc[t] += w.x * f.x + w.y * f.y + w.z * f.z + w.w * f.w;
            }
        }
    }
    const float bl = blin[(size_t)g * 256 + j];
    #pragma unroll
    for (int t = 0; t < T_; t++) fcs[t * 256 + j] = acc[t] + bl;
    __syncthreads();

    // lin1 = fc@W1^T + b1 ; beta = softplus(fc@W2^T + b2) ; gamma = lin1@Wd^T + bd
    float a1[T_], a2[T_];
    const float b1j = b1[j], b2j = b2[j];
    #pragma unroll
    for (int t = 0; t < T_; t++) { a1[t] = b1j; a2[t] = b2j; }
    {
        const float4* w1r = (const float4*)(W1 + (size_t)j * 256);
        const float4* w2r = (const float4*)(W2 + (size_t)j * 256);
        const float4* f4  = (const float4*)fcs;
        #pragma unroll 4
        for (int i4 = 0; i4 < 64; i4++) {
            float4 w1 = w1r[i4];
            float4 w2 = w2r[i4];
            #pragma unroll
            for (int t = 0; t < T_; t++) {
                float4 f = f4[t * 64 + i4];
                a1[t] += w1.x * f.x + w1.y * f.y + w1.z * f.z + w1.w * f.w;
                a2[t] += w2.x * f.x + w2.y * f.y + w2.z * f.z + w2.w * f.w;
            }
        }
    }
    const float wd = Wd[j];
    #pragma unroll
    for (int t = 0; t < T_; t++) {
        const size_t idx = ((size_t)g * T_ + t) * 256 + j;
        g_lin1[idx] = a1[t];
        float x = a2[t];
        out[OFF_BETA + idx] = (x > 20.0f) ? x : log1pf(__expf(x));
        float s = a1[t] * wd;
        #pragma unroll
        for (int o = 16; o > 0; o >>= 1) s += __shfl_xor_sync(0xffffffffu, s, o);
        if (lane == 0) red[t * 8 + warp] = s;
    }
    __syncthreads();
    if (j < T_) {
        float s = 0.0f;
        #pragma unroll
        for (int w = 0; w < 8; w++) s += red[j * 8 + w];
        out[OFF_GAMMA + (size_t)g * T_ + j] = s + bd[0];
    }
}

// ---------------------------------------------------------------------------
// Softmax over groups. Grid: (10, 4) x 64 threads; thread per (t, j).
// ---------------------------------------------------------------------------
__global__ void softmax_kernel(float* __restrict__ out)
{
    const int t = blockIdx.x;
    const int j = blockIdx.y * 64 + threadIdx.x;

    float v[G_];
    float m = -1e30f;
    #pragma unroll
    for (int g = 0; g < G_; g++) {
        v[g] = g_lin1[((size_t)g * T_ + t) * 256 + j];
        m = fmaxf(m, v[g]);
    }
    float s = 0.0f;
    #pragma unroll
    for (int g = 0; g < G_; g++) { v[g] = __expf(v[g] - m); s += v[g]; }
    const float inv = __fdividef(1.0f, s);
    #pragma unroll
    for (int g = 0; g < G_; g++)
        out[OFF_DELTA + ((size_t)g * T_ + t) * 256 + j] = v[g] * inv;
}

// ---------------------------------------------------------------------------
extern "C" void kernel_launch(void* const* d_in, const int* in_sizes, int n_in,
                              void* d_out, int out_size)
{
    const float* data = (const float*)d_in[0];
    const float* Wih0 = (const float*)d_in[1];
    const float* Whh0 = (const float*)d_in[2];
    const float* bih0 = (const float*)d_in[3];
    const float* bhh0 = (const float*)d_in[4];
    const float* Wih1 = (const float*)d_in[5];
    const float* Whh1 = (const float*)d_in[6];
    const float* bih1 = (const float*)d_in[7];
    const float* bhh1 = (const float*)d_in[8];
    const float* Wlin = (const float*)d_in[9];
    const float* blin = (const float*)d_in[10];
    const float* W1   = (const float*)d_in[11];
    const float* b1   = (const float*)d_in[12];
    const float* W2   = (const float*)d_in[13];
    const float* b2   = (const float*)d_in[14];
    const float* Wd   = (const float*)d_in[15];
    const float* bd   = (const float*)d_in[16];
    float* out = (float*)d_out;

    cudaFuncSetAttribute(lstm_persist_kernel,
                         cudaFuncAttributeMaxDynamicSharedMemorySize, SMEM_BYTES);

    // One dummy so ncu (-s 5 -c 1) lands on lstm_persist_kernel.
    dummy_kernel<<<1, 32>>>(0);

    lstm_persist_kernel<<<128, 512, SMEM_BYTES>>>(Wih0, Whh0, bih0, bhh0,
                                                  Wih1, Whh1, bih1, bhh1, data, out);
    tail_kernel<<<64, 256>>>(Wlin, blin, W1, b1, W2, b2, Wd, bd, out);
    softmax_kernel<<<dim3(10, 4), 64>>>(out);
}